// round 10
// baseline (speedup 1.0000x reference)
#include <cuda_runtime.h>

#define BB 4
#define NN 512
#define MM 512
#define LD 512
#define AG 256
#define ROWS (BB * NN)   // 2048

__device__ float g_dl[ROWS * AG];   // [row][a]
__device__ float g_cl[ROWS * AG];   // [row][a]

__device__ __forceinline__ float fast_tanh(float x) {
    float y;
    asm("tanh.approx.f32 %0, %1;" : "=f"(y) : "f"(x));
    return y;
}

// Packed 2xFP32 FMA (Blackwell): d = a * b + d, two fp32 lanes per instruction.
__device__ __forceinline__ void ffma2(unsigned long long& d,
                                      unsigned long long a,
                                      unsigned long long b) {
    asm("fma.rn.f32x2 %0, %1, %2, %3;" : "=l"(d) : "l"(a), "l"(b), "l"(d));
}
__device__ __forceinline__ unsigned long long splat2(float x) {
    unsigned long long r;
    asm("mov.b64 %0, {%1, %1};" : "=l"(r) : "f"(x));
    return r;
}
__device__ __forceinline__ float2 unpack2(unsigned long long v) {
    float2 f;
    asm("mov.b64 {%0, %1}, %2;" : "=f"(f.x), "=f"(f.y) : "l"(v));
    return f;
}

// ---------------------------------------------------------------------------
// Projection GEMM: out[row][a] = in[row][:] @ W + bias
// BM=64, BN=64, BK=16, 128 threads, per-thread 8(rows)x4(cols) as
// 4 row-pair-packed f32x2 accumulators x 4 cols. Row pairs come straight
// out of LDS.128 (no repacking); only b needs 4 splats.
// smem traffic: 1.5 B/FMA (was 2.0) -> LDS-bound ~25us; FFMA2 ~17us.
// ---------------------------------------------------------------------------
__global__ __launch_bounds__(128) void proj_kernel(
    const float* __restrict__ data, const float* __restrict__ crit,
    const float* __restrict__ Wl, const float* __restrict__ bl,
    const float* __restrict__ Wr, const float* __restrict__ br)
{
    __shared__ float As[2][16][68];   // [buf][k][m]  (row 272B -> 16B aligned)
    __shared__ float Bs[2][16][68];   // [buf][k][n]

    const float* A; const float* W; const float* bias; float* out;
    if (blockIdx.z == 0) { A = data; W = Wl; bias = bl; out = g_dl; }
    else                 { A = crit; W = Wr; bias = br; out = g_cl; }
    const int row0 = blockIdx.x * 64;
    const int col0 = blockIdx.y * 64;

    const int tid = threadIdx.x;
    // staging: A 64 rows x 16 k (2 float4/thread), B 16 k x 64 cols (2 float4)
    const int ar   = tid >> 1;            // 0..63
    const int ac   = (tid & 1) << 3;      // 0 or 8
    const int brow = tid >> 3;            // 0..15
    const int bcol = (tid & 7) << 3;      // 0..56
    // compute: row-group g (8 rows), col-group c4 (4 cols)
    const int g8 = (tid >> 4) << 3;       // 0,8,...,56
    const int c4 = (tid & 15) << 2;       // 0,4,...,60

    const float* Aptr = A + (size_t)(row0 + ar) * LD + ac;
    const float* Wptr = W + (size_t)brow * AG + col0 + bcol;

    unsigned long long acc[4][4];
#pragma unroll
    for (int i = 0; i < 4; i++)
#pragma unroll
        for (int j = 0; j < 4; j++) acc[i][j] = 0ull;

    // prologue: chunk 0 -> buf 0
    {
        float4 a0 = *(const float4*)(Aptr);
        float4 a1 = *(const float4*)(Aptr + 4);
        As[0][ac + 0][ar] = a0.x;  As[0][ac + 1][ar] = a0.y;
        As[0][ac + 2][ar] = a0.z;  As[0][ac + 3][ar] = a0.w;
        As[0][ac + 4][ar] = a1.x;  As[0][ac + 5][ar] = a1.y;
        As[0][ac + 6][ar] = a1.z;  As[0][ac + 7][ar] = a1.w;
        float4 b0 = *(const float4*)(Wptr);
        float4 b1 = *(const float4*)(Wptr + 4);
        *(float4*)&Bs[0][brow][bcol]     = b0;
        *(float4*)&Bs[0][brow][bcol + 4] = b1;
    }
    __syncthreads();

    int cur = 0;
    for (int k0 = 0; k0 < LD; k0 += 16) {
        float4 an0, an1, bn0, bn1;
        const bool more = (k0 + 16) < LD;
        if (more) {
            an0 = *(const float4*)(Aptr + k0 + 16);
            an1 = *(const float4*)(Aptr + k0 + 20);
            bn0 = *(const float4*)(Wptr + (size_t)(k0 + 16) * AG);
            bn1 = *(const float4*)(Wptr + (size_t)(k0 + 16) * AG + 4);
        }
#pragma unroll
        for (int k = 0; k < 16; k++) {
            // 8 a-rows as 4 packed pairs, straight from 16B-aligned smem
            ulonglong2 aL = *(const ulonglong2*)&As[cur][k][g8];
            ulonglong2 aH = *(const ulonglong2*)&As[cur][k][g8 + 4];
            float4 b4 = *(const float4*)&Bs[cur][k][c4];
            unsigned long long s0 = splat2(b4.x);
            unsigned long long s1 = splat2(b4.y);
            unsigned long long s2 = splat2(b4.z);
            unsigned long long s3 = splat2(b4.w);
            ffma2(acc[0][0], aL.x, s0); ffma2(acc[0][1], aL.x, s1);
            ffma2(acc[0][2], aL.x, s2); ffma2(acc[0][3], aL.x, s3);
            ffma2(acc[1][0], aL.y, s0); ffma2(acc[1][1], aL.y, s1);
            ffma2(acc[1][2], aL.y, s2); ffma2(acc[1][3], aL.y, s3);
            ffma2(acc[2][0], aH.x, s0); ffma2(acc[2][1], aH.x, s1);
            ffma2(acc[2][2], aH.x, s2); ffma2(acc[2][3], aH.x, s3);
            ffma2(acc[3][0], aH.y, s0); ffma2(acc[3][1], aH.y, s1);
            ffma2(acc[3][2], aH.y, s2); ffma2(acc[3][3], aH.y, s3);
        }
        if (more) {
            int nxt = cur ^ 1;
            As[nxt][ac + 0][ar] = an0.x;  As[nxt][ac + 1][ar] = an0.y;
            As[nxt][ac + 2][ar] = an0.z;  As[nxt][ac + 3][ar] = an0.w;
            As[nxt][ac + 4][ar] = an1.x;  As[nxt][ac + 5][ar] = an1.y;
            As[nxt][ac + 6][ar] = an1.z;  As[nxt][ac + 7][ar] = an1.w;
            *(float4*)&Bs[nxt][brow][bcol]     = bn0;
            *(float4*)&Bs[nxt][brow][bcol + 4] = bn1;
            __syncthreads();
            cur = nxt;
        }
    }

    // epilogue: acc[rp][c] lanes = rows (g8+2rp, g8+2rp+1), col c4+c
    const float4 bv = *(const float4*)&bias[col0 + c4];
#pragma unroll
    for (int rp = 0; rp < 4; rp++) {
        float2 p0 = unpack2(acc[rp][0]);
        float2 p1 = unpack2(acc[rp][1]);
        float2 p2 = unpack2(acc[rp][2]);
        float2 p3 = unpack2(acc[rp][3]);
        int r0 = row0 + g8 + (rp << 1);
        float4 v0 = make_float4(p0.x + bv.x, p1.x + bv.y, p2.x + bv.z, p3.x + bv.w);
        float4 v1 = make_float4(p0.y + bv.x, p1.y + bv.y, p2.y + bv.z, p3.y + bv.w);
        *(float4*)(out + (size_t)r0 * AG + col0 + c4)       = v0;
        *(float4*)(out + (size_t)(r0 + 1) * AG + col0 + c4) = v1;
    }
}

// ---------------------------------------------------------------------------
// Distance kernel: dists[b,n,m] = sum_a tanh(dl[b,n,a] + cl[b,m,a]) * agg[a]
// MUFU-bound at the HW floor (16 tanh/cyc/SM): ~67us. Unchanged from R9.
// ---------------------------------------------------------------------------
__global__ __launch_bounds__(256) void dist_kernel(
    const float* __restrict__ agg, float* __restrict__ out)
{
    __shared__ float dls[64][34];
    __shared__ float cls[64][34];
    __shared__ float aggs[AG];

    const int b  = blockIdx.z;
    const int n0 = blockIdx.x << 5;
    const int m0 = blockIdx.y << 5;
    const int tid = threadIdx.x;
    const int ty2 = (tid >> 4) << 1;
    const int tx2 = (tid & 15) << 1;

    aggs[tid] = agg[tid];

    const float* dlb = g_dl + (size_t)(b * NN + n0) * AG;
    const float* clb = g_cl + (size_t)(b * MM + m0) * AG;

    float a00 = 0.f, a01 = 0.f, a10 = 0.f, a11 = 0.f;

    for (int a0 = 0; a0 < AG; a0 += 64) {
        __syncthreads();
#pragma unroll
        for (int h = 0; h < 2; h++) {
            int idx = tid + (h << 8);
            int r   = idx >> 4;
            int a4  = (idx & 15) << 2;
            float4 v = *(const float4*)(dlb + (size_t)r * AG + a0 + a4);
            dls[a4 + 0][r] = v.x;
            dls[a4 + 1][r] = v.y;
            dls[a4 + 2][r] = v.z;
            dls[a4 + 3][r] = v.w;
            float4 w = *(const float4*)(clb + (size_t)r * AG + a0 + a4);
            cls[a4 + 0][r] = w.x;
            cls[a4 + 1][r] = w.y;
            cls[a4 + 2][r] = w.z;
            cls[a4 + 3][r] = w.w;
        }
        __syncthreads();

#pragma unroll 4
        for (int a = 0; a < 64; a++) {
            float2 d = *(const float2*)&dls[a][ty2];
            float2 c = *(const float2*)&cls[a][tx2];
            float g = aggs[a0 + a];
            a00 = fmaf(fast_tanh(d.x + c.x), g, a00);
            a01 = fmaf(fast_tanh(d.x + c.y), g, a01);
            a10 = fmaf(fast_tanh(d.y + c.x), g, a10);
            a11 = fmaf(fast_tanh(d.y + c.y), g, a11);
        }
    }

    float* o0 = out + ((size_t)(b * NN + n0 + ty2) << 9) + m0 + tx2;
    float* o1 = o0 + MM;
    *(float2*)o0 = make_float2(a00, a01);
    *(float2*)o1 = make_float2(a10, a11);
}

extern "C" void kernel_launch(void* const* d_in, const int* in_sizes, int n_in,
                              void* d_out, int out_size) {
    const float* data = (const float*)d_in[0];
    const float* crit = (const float*)d_in[1];
    const float* Wl   = (const float*)d_in[2];
    const float* bl   = (const float*)d_in[3];
    const float* Wr   = (const float*)d_in[4];
    const float* br   = (const float*)d_in[5];
    const float* agg  = (const float*)d_in[6];
    float* out = (float*)d_out;

    proj_kernel<<<dim3(32, 4, 2), 128>>>(data, crit, Wl, bl, Wr, br);
    dist_kernel<<<dim3(16, 16, 4), 256>>>(agg, out);
}